// round 9
// baseline (speedup 1.0000x reference)
#include <cuda_runtime.h>
#include <math.h>

// ---------------- Fixed problem geometry ----------------
#define B_      64
#define N_      1024
#define E_      655360
#define H_      128
#define K1_     820
#define K2_     656
#define NODES1  (B_ * N_)    // 65536
#define NODES2  (B_ * K1_)   // 52480
#define NODES3  (B_ * K2_)   // 41984

// ---------------- Scratch (static device globals; no runtime alloc) ----------------
__device__ float g_s     [NODES1 * 128];
__device__ float g_cnt   [NODES1];
__device__ float g_h1    [NODES1 * 128];
__device__ float g_score1[NODES1];
__device__ int   g_perm1 [NODES2];
__device__ int   g_inv1  [NODES1];
__device__ float g_h1p   [NODES2 * 128];
__device__ float g_x1    [B_ * 256];
__device__ float g_s2    [NODES2 * 128];
__device__ float g_cnt2  [NODES2];
__device__ float g_h2    [NODES2 * 128];
__device__ float g_score2[NODES2];
__device__ int   g_perm2 [NODES3];
__device__ float g_h2p   [NODES3 * 128];
__device__ float g_x2    [B_ * 256];

// ---------------- Edge aggregation (layer 1): s[dst] += x[src], cnt[dst] += 1 ----------------
__global__ void agg1_kernel(const float* __restrict__ x,
                            const int* __restrict__ src, const int* __restrict__ dst,
                            float* __restrict__ s, float* __restrict__ cnt)
{
    int g = blockIdx.x * blockDim.x + threadIdx.x;
    int e = g >> 5, lane = g & 31;
    if (e >= E_) return;
    int sn = src[e], dn = dst[e];
    float4 v = ((const float4*)(x + (size_t)sn * 128))[lane];
    atomicAdd(((float4*)(s + (size_t)dn * 128)) + lane, v);
    if (lane == 0) atomicAdd(cnt + dn, 1.0f);
}

// ---------------- Edge aggregation (layer 2) through inv-relabel; drop masked edges ------------
__global__ void agg2_kernel(const float* __restrict__ h1p,
                            const int* __restrict__ src, const int* __restrict__ dst,
                            const int* __restrict__ inv,
                            float* __restrict__ s2, float* __restrict__ cnt2)
{
    int g = blockIdx.x * blockDim.x + threadIdx.x;
    int e = g >> 5, lane = g & 31;
    if (e >= E_) return;
    int ns = inv[src[e]];
    int nd = inv[dst[e]];
    if (ns < 0 || nd < 0) return;   // uniform across the warp (same edge)
    float4 v = ((const float4*)(h1p + (size_t)ns * 128))[lane];
    atomicAdd(((float4*)(s2 + (size_t)nd * 128)) + lane, v);
    if (lane == 0) atomicAdd(cnt2 + nd, 1.0f);
}

// ---------------- mean: s[i][:] /= max(cnt[i],1), in place (float4 granularity) ---------------
__global__ void meandiv_kernel(float* __restrict__ s, const float* __restrict__ cnt, int nrows)
{
    int i = blockIdx.x * blockDim.x + threadIdx.x;     // over nrows*32 float4s
    if (i >= nrows * 32) return;
    float c = fmaxf(cnt[i >> 5], 1.0f);
    float4 v = ((const float4*)s)[i];
    v.x /= c; v.y /= c; v.z /= c; v.w /= c;
    ((float4*)s)[i] = v;
}

// ---------------- Fused SAGE GEMM: out = relu([mean|xin] @ [Wl;Wr] + bias) -------------------
// 256 threads/block, 64-row x 128-col tile, 8x4 per-thread micro-tile, K=256 in chunks of 16.
__global__ __launch_bounds__(256) void sage_gemm_kernel(
    const float* __restrict__ mean, const float* __restrict__ xin,
    const float* __restrict__ Wl,   const float* __restrict__ Wr,
    const float* __restrict__ bias, float* __restrict__ outp, int rows)
{
    __shared__ float As[16 * 68];    // [k][row], padded to 68 (16B-aligned rows, low conflicts)
    __shared__ float Bs[16 * 128];   // [k][col]

    int tid = threadIdx.x;
    int tx = tid & 31;               // col group: cols tx*4 .. tx*4+3
    int ty = tid >> 5;               // row group: rows ty*8 .. ty*8+7
    int row0 = blockIdx.x * 64;
    if (row0 >= rows) return;

    float acc[8][4];
    #pragma unroll
    for (int r = 0; r < 8; r++)
        #pragma unroll
        for (int c = 0; c < 4; c++) acc[r][c] = 0.0f;

    for (int k0 = 0; k0 < 256; k0 += 16) {
        // load A tile: 64 rows x 16 k, transposed into As[k][row]
        #pragma unroll
        for (int i = 0; i < 4; i++) {
            int e = tid + i * 256;
            int kl = e & 15, r = e >> 4;
            int kg = k0 + kl;
            float v = (kg < 128) ? mean[(size_t)(row0 + r) * 128 + kg]
                                 : xin [(size_t)(row0 + r) * 128 + (kg - 128)];
            As[kl * 68 + r] = v;
        }
        // load B tile: 16 k x 128 cols
        #pragma unroll
        for (int i = 0; i < 8; i++) {
            int e = tid + i * 256;
            int kl = e >> 7, c = e & 127;
            int kg = k0 + kl;
            Bs[kl * 128 + c] = (kg < 128) ? Wl[kg * 128 + c] : Wr[(kg - 128) * 128 + c];
        }
        __syncthreads();

        #pragma unroll
        for (int kk = 0; kk < 16; kk++) {
            float4 b4 = *(const float4*)&Bs[kk * 128 + tx * 4];
            float4 a0 = *(const float4*)&As[kk * 68 + ty * 8];
            float4 a1 = *(const float4*)&As[kk * 68 + ty * 8 + 4];
            float a[8] = {a0.x, a0.y, a0.z, a0.w, a1.x, a1.y, a1.z, a1.w};
            #pragma unroll
            for (int r = 0; r < 8; r++) {
                acc[r][0] += a[r] * b4.x;
                acc[r][1] += a[r] * b4.y;
                acc[r][2] += a[r] * b4.z;
                acc[r][3] += a[r] * b4.w;
            }
        }
        __syncthreads();
    }

    float4 bb = *(const float4*)&bias[tx * 4];
    #pragma unroll
    for (int r = 0; r < 8; r++) {
        int row = row0 + ty * 8 + r;
        float4 v;
        v.x = fmaxf(acc[r][0] + bb.x, 0.0f);
        v.y = fmaxf(acc[r][1] + bb.y, 0.0f);
        v.z = fmaxf(acc[r][2] + bb.z, 0.0f);
        v.w = fmaxf(acc[r][3] + bb.w, 0.0f);
        *(float4*)&outp[(size_t)row * 128 + tx * 4] = v;
    }
}

// ---------------- score = tanh(h . w / ||w||), one warp per node -----------------------------
__global__ void score_kernel(const float* __restrict__ h, const float* __restrict__ w,
                             float* __restrict__ score, int n)
{
    int g = blockIdx.x * blockDim.x + threadIdx.x;
    int node = g >> 5, lane = g & 31;
    if (node >= n) return;
    float4 wv = ((const float4*)w)[lane];
    float4 hv = ((const float4*)(h + (size_t)node * 128))[lane];
    float d  = hv.x * wv.x + hv.y * wv.y + hv.z * wv.z + hv.w * wv.w;
    float nw = wv.x * wv.x + wv.y * wv.y + wv.z * wv.z + wv.w * wv.w;
    #pragma unroll
    for (int o = 16; o; o >>= 1) {
        d  += __shfl_xor_sync(0xFFFFFFFFu, d, o);
        nw += __shfl_xor_sync(0xFFFFFFFFu, nw, o);
    }
    if (lane == 0) score[node] = tanhf(d * rsqrtf(nw));
}

// ---------------- TopK pool: per-graph bitonic sort (desc score, asc idx), compact by idx ----
__global__ __launch_bounds__(1024) void topk_kernel(
    const float* __restrict__ score, int* __restrict__ perm, int* __restrict__ inv,
    int n_per, int K)
{
    __shared__ unsigned long long keys[1024];
    __shared__ int keep[1024];
    __shared__ int scan[1024];
    int tid = threadIdx.x, b = blockIdx.x;

    float sc = (tid < n_per) ? score[b * n_per + tid] : __int_as_float(0xFF800000); // -inf pad
    unsigned int bits = __float_as_uint(sc);
    unsigned int u = (bits & 0x80000000u) ? ~bits : (bits | 0x80000000u); // order-preserving map
    keys[tid] = ((unsigned long long)u << 32) | (unsigned int)(1023 - tid); // ties: lower idx wins
    keep[tid] = 0;
    __syncthreads();

    // bitonic sort, descending
    for (int k = 2; k <= 1024; k <<= 1) {
        for (int j = k >> 1; j > 0; j >>= 1) {
            int ixj = tid ^ j;
            if (ixj > tid) {
                unsigned long long a = keys[tid], c = keys[ixj];
                bool up = ((tid & k) == 0);
                bool sw = up ? (a < c) : (a > c);
                if (sw) { keys[tid] = c; keys[ixj] = a; }
            }
            __syncthreads();
        }
    }

    if (tid < K) {
        int idx = 1023 - (int)(keys[tid] & 0xFFFFFFFFu);
        keep[idx] = 1;
    }
    __syncthreads();

    int v = keep[tid];
    scan[tid] = v;
    __syncthreads();
    for (int off = 1; off < 1024; off <<= 1) {
        int t = (tid >= off) ? scan[tid - off] : 0;
        __syncthreads();
        scan[tid] += t;
        __syncthreads();
    }

    if (tid < n_per) {
        int old = b * n_per + tid;
        if (v) {
            int newid = b * K + (scan[tid] - 1);   // inclusive scan - own flag = exclusive pos
            perm[newid] = old;
            if (inv) inv[old] = newid;
        } else if (inv) {
            inv[old] = -1;
        }
    }
}

// ---------------- gate: hp[new] = h[perm[new]] * score[perm[new]], one warp per node ----------
__global__ void gate_kernel(const float* __restrict__ h, const float* __restrict__ score,
                            const int* __restrict__ perm, float* __restrict__ hp, int total)
{
    int g = blockIdx.x * blockDim.x + threadIdx.x;
    int nid = g >> 5, lane = g & 31;
    if (nid >= total) return;
    int old = perm[nid];
    float sc = score[old];
    float4 v = ((const float4*)(h + (size_t)old * 128))[lane];
    v.x *= sc; v.y *= sc; v.z *= sc; v.w *= sc;
    ((float4*)(hp + (size_t)nid * 128))[lane] = v;
}

// ---------------- readout: [mean over K | max over K] per graph ------------------------------
__global__ void readout_kernel(const float* __restrict__ hp, float* __restrict__ xout, int K)
{
    __shared__ float ss[4][128], sm[4][128];
    int b = blockIdx.x;
    int tid = threadIdx.x;          // 512 threads
    int f = tid & 127, ty = tid >> 7;
    float sum = 0.0f, mx = __int_as_float(0xFF800000);
    for (int r = ty; r < K; r += 4) {
        float v = hp[((size_t)(b * K + r)) * 128 + f];
        sum += v;
        mx = fmaxf(mx, v);
    }
    ss[ty][f] = sum; sm[ty][f] = mx;
    __syncthreads();
    if (ty == 0) {
        float s = ss[0][f] + ss[1][f] + ss[2][f] + ss[3][f];
        float m = fmaxf(fmaxf(sm[0][f], sm[1][f]), fmaxf(sm[2][f], sm[3][f]));
        xout[b * 256 + f] = s / (float)K;
        xout[b * 256 + 128 + f] = m;
    }
}

// ---------------- final MLP: out = relu((x1+x2)@fW1+fb1) @ fW2 + fb2 --------------------------
__global__ void mlp_kernel(const float* __restrict__ x1, const float* __restrict__ x2,
                           const float* __restrict__ fW1, const float* __restrict__ fb1,
                           const float* __restrict__ fW2, const float* __restrict__ fb2,
                           float* __restrict__ out)
{
    __shared__ float row[256];
    __shared__ float zs[128];
    int b = blockIdx.x, t = threadIdx.x;   // 128 threads
    row[t]       = x1[b * 256 + t]       + x2[b * 256 + t];
    row[t + 128] = x1[b * 256 + 128 + t] + x2[b * 256 + 128 + t];
    __syncthreads();
    float acc = fb1[t];
    #pragma unroll 8
    for (int k = 0; k < 256; k++) acc += row[k] * fW1[k * 128 + t];
    zs[t] = fmaxf(acc, 0.0f);
    __syncthreads();
    if (t < 10) {
        float o = fb2[t];
        #pragma unroll 8
        for (int k = 0; k < 128; k++) o += zs[k] * fW2[k * 10 + t];
        out[b * 10 + t] = o;
    }
}

// ---------------- host orchestration ----------------------------------------------------------
extern "C" void kernel_launch(void* const* d_in, const int* in_sizes, int n_in,
                              void* d_out, int out_size)
{
    (void)in_sizes; (void)n_in; (void)out_size;
    const float* x   = (const float*)d_in[0];
    const int*   ei  = (const int*)d_in[1];
    const float* Wl1 = (const float*)d_in[3];
    const float* bl1 = (const float*)d_in[4];
    const float* Wr1 = (const float*)d_in[5];
    const float* Wl2 = (const float*)d_in[6];
    const float* bl2 = (const float*)d_in[7];
    const float* Wr2 = (const float*)d_in[8];
    const float* pw1 = (const float*)d_in[9];
    const float* pw2 = (const float*)d_in[10];
    const float* fW1 = (const float*)d_in[11];
    const float* fb1 = (const float*)d_in[12];
    const float* fW2 = (const float*)d_in[13];
    const float* fb2 = (const float*)d_in[14];
    float* out = (float*)d_out;

    const int* src = ei;
    const int* dst = ei + E_;

    // device pointers for scratch symbols
    float *ps, *pcnt, *ph1, *psc1, *ph1p, *px1, *ps2, *pcnt2, *ph2, *psc2, *ph2p, *px2;
    int *pperm1, *pinv1, *pperm2;
    cudaGetSymbolAddress((void**)&ps,     g_s);
    cudaGetSymbolAddress((void**)&pcnt,   g_cnt);
    cudaGetSymbolAddress((void**)&ph1,    g_h1);
    cudaGetSymbolAddress((void**)&psc1,   g_score1);
    cudaGetSymbolAddress((void**)&pperm1, g_perm1);
    cudaGetSymbolAddress((void**)&pinv1,  g_inv1);
    cudaGetSymbolAddress((void**)&ph1p,   g_h1p);
    cudaGetSymbolAddress((void**)&px1,    g_x1);
    cudaGetSymbolAddress((void**)&ps2,    g_s2);
    cudaGetSymbolAddress((void**)&pcnt2,  g_cnt2);
    cudaGetSymbolAddress((void**)&ph2,    g_h2);
    cudaGetSymbolAddress((void**)&psc2,   g_score2);
    cudaGetSymbolAddress((void**)&pperm2, g_perm2);
    cudaGetSymbolAddress((void**)&ph2p,   g_h2p);
    cudaGetSymbolAddress((void**)&px2,    g_x2);

    // zero accumulators
    cudaMemsetAsync(ps,    0, sizeof(float) * NODES1 * 128);
    cudaMemsetAsync(pcnt,  0, sizeof(float) * NODES1);
    cudaMemsetAsync(ps2,   0, sizeof(float) * NODES2 * 128);
    cudaMemsetAsync(pcnt2, 0, sizeof(float) * NODES2);

    // ---- layer 1 ----
    agg1_kernel<<<(E_ * 32) / 256, 256>>>(x, src, dst, ps, pcnt);
    meandiv_kernel<<<(NODES1 * 32) / 256, 256>>>(ps, pcnt, NODES1);
    sage_gemm_kernel<<<NODES1 / 64, 256>>>(ps, x, Wl1, Wr1, bl1, ph1, NODES1);
    score_kernel<<<(NODES1 * 32) / 256, 256>>>(ph1, pw1, psc1, NODES1);
    topk_kernel<<<B_, 1024>>>(psc1, pperm1, pinv1, N_, K1_);
    gate_kernel<<<(NODES2 * 32) / 256, 256>>>(ph1, psc1, pperm1, ph1p, NODES2);
    readout_kernel<<<B_, 512>>>(ph1p, px1, K1_);

    // ---- layer 2 ----
    agg2_kernel<<<(E_ * 32) / 256, 256>>>(ph1p, src, dst, pinv1, ps2, pcnt2);
    meandiv_kernel<<<(NODES2 * 32) / 256, 256>>>(ps2, pcnt2, NODES2);
    sage_gemm_kernel<<<NODES2 / 64, 256>>>(ps2, ph1p, Wl2, Wr2, bl2, ph2, NODES2);
    score_kernel<<<(NODES2 * 32) / 256, 256>>>(ph2, pw2, psc2, NODES2);
    topk_kernel<<<B_, 1024>>>(psc2, pperm2, (int*)0, K1_, K2_);
    gate_kernel<<<(NODES3 * 32) / 256, 256>>>(ph2, psc2, pperm2, ph2p, NODES3);
    readout_kernel<<<B_, 512>>>(ph2p, px2, K2_);

    // ---- head ----
    mlp_kernel<<<B_, 128>>>(px1, px2, fW1, fb1, fW2, fb2, out);
}

// round 10
// speedup vs baseline: 1.0093x; 1.0093x over previous
#include <cuda_runtime.h>
#include <math.h>

// ---------------- Fixed problem geometry ----------------
#define B_      64
#define N_      1024
#define E_      655360
#define H_      128
#define K1_     820
#define K2_     656
#define NODES1  (B_ * N_)    // 65536
#define NODES2  (B_ * K1_)   // 52480
#define NODES3  (B_ * K2_)   // 41984

// ---------------- Scratch (static device globals; no runtime alloc) ----------------
__device__ float g_s     [NODES1 * 128];
__device__ float g_cnt   [NODES1];
__device__ float g_h1    [NODES1 * 128];
__device__ float g_score1[NODES1];
__device__ int   g_perm1 [NODES2];
__device__ int   g_inv1  [NODES1];
__device__ float g_h1p   [NODES2 * 128];
__device__ float g_x1    [B_ * 256];
__device__ float g_s2    [NODES2 * 128];
__device__ float g_cnt2  [NODES2];
__device__ float g_h2    [NODES2 * 128];
__device__ float g_score2[NODES2];
__device__ int   g_perm2 [NODES3];
__device__ float g_h2p   [NODES3 * 128];
__device__ float g_x2    [B_ * 256];

// ---------------- Edge aggregation (layer 1): s[dst] += x[src], cnt[dst] += 1 ----------------
__global__ void agg1_kernel(const float* __restrict__ x,
                            const int* __restrict__ src, const int* __restrict__ dst,
                            float* __restrict__ s, float* __restrict__ cnt)
{
    int g = blockIdx.x * blockDim.x + threadIdx.x;
    int e = g >> 5, lane = g & 31;
    if (e >= E_) return;
    int sn = src[e], dn = dst[e];
    float4 v = ((const float4*)(x + (size_t)sn * 128))[lane];
    atomicAdd(((float4*)(s + (size_t)dn * 128)) + lane, v);
    if (lane == 0) atomicAdd(cnt + dn, 1.0f);
}

// ---------------- Edge aggregation (layer 2) through inv-relabel; drop masked edges ------------
__global__ void agg2_kernel(const float* __restrict__ h1p,
                            const int* __restrict__ src, const int* __restrict__ dst,
                            const int* __restrict__ inv,
                            float* __restrict__ s2, float* __restrict__ cnt2)
{
    int g = blockIdx.x * blockDim.x + threadIdx.x;
    int e = g >> 5, lane = g & 31;
    if (e >= E_) return;
    int ns = inv[src[e]];
    int nd = inv[dst[e]];
    if (ns < 0 || nd < 0) return;   // uniform across the warp (same edge)
    float4 v = ((const float4*)(h1p + (size_t)ns * 128))[lane];
    atomicAdd(((float4*)(s2 + (size_t)nd * 128)) + lane, v);
    if (lane == 0) atomicAdd(cnt2 + nd, 1.0f);
}

// ---------------- mean: s[i][:] /= max(cnt[i],1), in place (float4 granularity) ---------------
__global__ void meandiv_kernel(float* __restrict__ s, const float* __restrict__ cnt, int nrows)
{
    int i = blockIdx.x * blockDim.x + threadIdx.x;     // over nrows*32 float4s
    if (i >= nrows * 32) return;
    float c = fmaxf(cnt[i >> 5], 1.0f);
    float4 v = ((const float4*)s)[i];
    v.x /= c; v.y /= c; v.z /= c; v.w /= c;
    ((float4*)s)[i] = v;
}

// ---------------- Fused SAGE GEMM: out = relu([mean|xin] @ [Wl;Wr] + bias) -------------------
// 256 threads/block, 64-row x 128-col tile, 8x4 per-thread micro-tile, K=256 in chunks of 16.
__global__ __launch_bounds__(256) void sage_gemm_kernel(
    const float* __restrict__ mean, const float* __restrict__ xin,
    const float* __restrict__ Wl,   const float* __restrict__ Wr,
    const float* __restrict__ bias, float* __restrict__ outp, int rows)
{
    __shared__ float As[16 * 68];    // [k][row], padded to 68 (16B-aligned rows, low conflicts)
    __shared__ float Bs[16 * 128];   // [k][col]

    int tid = threadIdx.x;
    int tx = tid & 31;               // col group: cols tx*4 .. tx*4+3
    int ty = tid >> 5;               // row group: rows ty*8 .. ty*8+7
    int row0 = blockIdx.x * 64;
    if (row0 >= rows) return;

    float acc[8][4];
    #pragma unroll
    for (int r = 0; r < 8; r++)
        #pragma unroll
        for (int c = 0; c < 4; c++) acc[r][c] = 0.0f;

    for (int k0 = 0; k0 < 256; k0 += 16) {
        // load A tile: 64 rows x 16 k, transposed into As[k][row]
        #pragma unroll
        for (int i = 0; i < 4; i++) {
            int e = tid + i * 256;
            int kl = e & 15, r = e >> 4;
            int kg = k0 + kl;
            float v = (kg < 128) ? mean[(size_t)(row0 + r) * 128 + kg]
                                 : xin [(size_t)(row0 + r) * 128 + (kg - 128)];
            As[kl * 68 + r] = v;
        }
        // load B tile: 16 k x 128 cols
        #pragma unroll
        for (int i = 0; i < 8; i++) {
            int e = tid + i * 256;
            int kl = e >> 7, c = e & 127;
            int kg = k0 + kl;
            Bs[kl * 128 + c] = (kg < 128) ? Wl[kg * 128 + c] : Wr[(kg - 128) * 128 + c];
        }
        __syncthreads();

        #pragma unroll
        for (int kk = 0; kk < 16; kk++) {
            float4 b4 = *(const float4*)&Bs[kk * 128 + tx * 4];
            float4 a0 = *(const float4*)&As[kk * 68 + ty * 8];
            float4 a1 = *(const float4*)&As[kk * 68 + ty * 8 + 4];
            float a[8] = {a0.x, a0.y, a0.z, a0.w, a1.x, a1.y, a1.z, a1.w};
            #pragma unroll
            for (int r = 0; r < 8; r++) {
                acc[r][0] += a[r] * b4.x;
                acc[r][1] += a[r] * b4.y;
                acc[r][2] += a[r] * b4.z;
                acc[r][3] += a[r] * b4.w;
            }
        }
        __syncthreads();
    }

    float4 bb = *(const float4*)&bias[tx * 4];
    #pragma unroll
    for (int r = 0; r < 8; r++) {
        int row = row0 + ty * 8 + r;
        float4 v;
        v.x = fmaxf(acc[r][0] + bb.x, 0.0f);
        v.y = fmaxf(acc[r][1] + bb.y, 0.0f);
        v.z = fmaxf(acc[r][2] + bb.z, 0.0f);
        v.w = fmaxf(acc[r][3] + bb.w, 0.0f);
        *(float4*)&outp[(size_t)row * 128 + tx * 4] = v;
    }
}

// ---------------- score = tanh(h . w / ||w||), one warp per node -----------------------------
__global__ void score_kernel(const float* __restrict__ h, const float* __restrict__ w,
                             float* __restrict__ score, int n)
{
    int g = blockIdx.x * blockDim.x + threadIdx.x;
    int node = g >> 5, lane = g & 31;
    if (node >= n) return;
    float4 wv = ((const float4*)w)[lane];
    float4 hv = ((const float4*)(h + (size_t)node * 128))[lane];
    float d  = hv.x * wv.x + hv.y * wv.y + hv.z * wv.z + hv.w * wv.w;
    float nw = wv.x * wv.x + wv.y * wv.y + wv.z * wv.z + wv.w * wv.w;
    #pragma unroll
    for (int o = 16; o; o >>= 1) {
        d  += __shfl_xor_sync(0xFFFFFFFFu, d, o);
        nw += __shfl_xor_sync(0xFFFFFFFFu, nw, o);
    }
    if (lane == 0) score[node] = tanhf(d * rsqrtf(nw));
}

// ---------------- TopK pool: per-graph bitonic sort (desc score, asc idx), compact by idx ----
__global__ __launch_bounds__(1024) void topk_kernel(
    const float* __restrict__ score, int* __restrict__ perm, int* __restrict__ inv,
    int n_per, int K)
{
    __shared__ unsigned long long keys[1024];
    __shared__ int keep[1024];
    __shared__ int scan[1024];
    int tid = threadIdx.x, b = blockIdx.x;

    float sc = (tid < n_per) ? score[b * n_per + tid] : __int_as_float(0xFF800000); // -inf pad
    unsigned int bits = __float_as_uint(sc);
    unsigned int u = (bits & 0x80000000u) ? ~bits : (bits | 0x80000000u); // order-preserving map
    keys[tid] = ((unsigned long long)u << 32) | (unsigned int)(1023 - tid); // ties: lower idx wins
    keep[tid] = 0;
    __syncthreads();

    // bitonic sort, descending
    for (int k = 2; k <= 1024; k <<= 1) {
        for (int j = k >> 1; j > 0; j >>= 1) {
            int ixj = tid ^ j;
            if (ixj > tid) {
                unsigned long long a = keys[tid], c = keys[ixj];
                bool up = ((tid & k) == 0);
                bool sw = up ? (a < c) : (a > c);
                if (sw) { keys[tid] = c; keys[ixj] = a; }
            }
            __syncthreads();
        }
    }

    if (tid < K) {
        int idx = 1023 - (int)(keys[tid] & 0xFFFFFFFFu);
        keep[idx] = 1;
    }
    __syncthreads();

    int v = keep[tid];
    scan[tid] = v;
    __syncthreads();
    for (int off = 1; off < 1024; off <<= 1) {
        int t = (tid >= off) ? scan[tid - off] : 0;
        __syncthreads();
        scan[tid] += t;
        __syncthreads();
    }

    if (tid < n_per) {
        int old = b * n_per + tid;
        if (v) {
            int newid = b * K + (scan[tid] - 1);   // inclusive scan - own flag = exclusive pos
            perm[newid] = old;
            if (inv) inv[old] = newid;
        } else if (inv) {
            inv[old] = -1;
        }
    }
}

// ---------------- gate: hp[new] = h[perm[new]] * score[perm[new]], one warp per node ----------
__global__ void gate_kernel(const float* __restrict__ h, const float* __restrict__ score,
                            const int* __restrict__ perm, float* __restrict__ hp, int total)
{
    int g = blockIdx.x * blockDim.x + threadIdx.x;
    int nid = g >> 5, lane = g & 31;
    if (nid >= total) return;
    int old = perm[nid];
    float sc = score[old];
    float4 v = ((const float4*)(h + (size_t)old * 128))[lane];
    v.x *= sc; v.y *= sc; v.z *= sc; v.w *= sc;
    ((float4*)(hp + (size_t)nid * 128))[lane] = v;
}

// ---------------- readout: [mean over K | max over K] per graph ------------------------------
__global__ void readout_kernel(const float* __restrict__ hp, float* __restrict__ xout, int K)
{
    __shared__ float ss[4][128], sm[4][128];
    int b = blockIdx.x;
    int tid = threadIdx.x;          // 512 threads
    int f = tid & 127, ty = tid >> 7;
    float sum = 0.0f, mx = __int_as_float(0xFF800000);
    for (int r = ty; r < K; r += 4) {
        float v = hp[((size_t)(b * K + r)) * 128 + f];
        sum += v;
        mx = fmaxf(mx, v);
    }
    ss[ty][f] = sum; sm[ty][f] = mx;
    __syncthreads();
    if (ty == 0) {
        float s = ss[0][f] + ss[1][f] + ss[2][f] + ss[3][f];
        float m = fmaxf(fmaxf(sm[0][f], sm[1][f]), fmaxf(sm[2][f], sm[3][f]));
        xout[b * 256 + f] = s / (float)K;
        xout[b * 256 + 128 + f] = m;
    }
}

// ---------------- final MLP: out = relu((x1+x2)@fW1+fb1) @ fW2 + fb2 --------------------------
__global__ void mlp_kernel(const float* __restrict__ x1, const float* __restrict__ x2,
                           const float* __restrict__ fW1, const float* __restrict__ fb1,
                           const float* __restrict__ fW2, const float* __restrict__ fb2,
                           float* __restrict__ out)
{
    __shared__ float row[256];
    __shared__ float zs[128];
    int b = blockIdx.x, t = threadIdx.x;   // 128 threads
    row[t]       = x1[b * 256 + t]       + x2[b * 256 + t];
    row[t + 128] = x1[b * 256 + 128 + t] + x2[b * 256 + 128 + t];
    __syncthreads();
    float acc = fb1[t];
    #pragma unroll 8
    for (int k = 0; k < 256; k++) acc += row[k] * fW1[k * 128 + t];
    zs[t] = fmaxf(acc, 0.0f);
    __syncthreads();
    if (t < 10) {
        float o = fb2[t];
        #pragma unroll 8
        for (int k = 0; k < 128; k++) o += zs[k] * fW2[k * 10 + t];
        out[b * 10 + t] = o;
    }
}

// ---------------- host orchestration ----------------------------------------------------------
extern "C" void kernel_launch(void* const* d_in, const int* in_sizes, int n_in,
                              void* d_out, int out_size)
{
    (void)in_sizes; (void)n_in; (void)out_size;
    const float* x   = (const float*)d_in[0];
    const int*   ei  = (const int*)d_in[1];
    const float* Wl1 = (const float*)d_in[3];
    const float* bl1 = (const float*)d_in[4];
    const float* Wr1 = (const float*)d_in[5];
    const float* Wl2 = (const float*)d_in[6];
    const float* bl2 = (const float*)d_in[7];
    const float* Wr2 = (const float*)d_in[8];
    const float* pw1 = (const float*)d_in[9];
    const float* pw2 = (const float*)d_in[10];
    const float* fW1 = (const float*)d_in[11];
    const float* fb1 = (const float*)d_in[12];
    const float* fW2 = (const float*)d_in[13];
    const float* fb2 = (const float*)d_in[14];
    float* out = (float*)d_out;

    const int* src = ei;
    const int* dst = ei + E_;

    // device pointers for scratch symbols
    float *ps, *pcnt, *ph1, *psc1, *ph1p, *px1, *ps2, *pcnt2, *ph2, *psc2, *ph2p, *px2;
    int *pperm1, *pinv1, *pperm2;
    cudaGetSymbolAddress((void**)&ps,     g_s);
    cudaGetSymbolAddress((void**)&pcnt,   g_cnt);
    cudaGetSymbolAddress((void**)&ph1,    g_h1);
    cudaGetSymbolAddress((void**)&psc1,   g_score1);
    cudaGetSymbolAddress((void**)&pperm1, g_perm1);
    cudaGetSymbolAddress((void**)&pinv1,  g_inv1);
    cudaGetSymbolAddress((void**)&ph1p,   g_h1p);
    cudaGetSymbolAddress((void**)&px1,    g_x1);
    cudaGetSymbolAddress((void**)&ps2,    g_s2);
    cudaGetSymbolAddress((void**)&pcnt2,  g_cnt2);
    cudaGetSymbolAddress((void**)&ph2,    g_h2);
    cudaGetSymbolAddress((void**)&psc2,   g_score2);
    cudaGetSymbolAddress((void**)&pperm2, g_perm2);
    cudaGetSymbolAddress((void**)&ph2p,   g_h2p);
    cudaGetSymbolAddress((void**)&px2,    g_x2);

    // zero accumulators
    cudaMemsetAsync(ps,    0, sizeof(float) * NODES1 * 128);
    cudaMemsetAsync(pcnt,  0, sizeof(float) * NODES1);
    cudaMemsetAsync(ps2,   0, sizeof(float) * NODES2 * 128);
    cudaMemsetAsync(pcnt2, 0, sizeof(float) * NODES2);

    // ---- layer 1 ----
    agg1_kernel<<<(E_ * 32) / 256, 256>>>(x, src, dst, ps, pcnt);
    meandiv_kernel<<<(NODES1 * 32) / 256, 256>>>(ps, pcnt, NODES1);
    sage_gemm_kernel<<<NODES1 / 64, 256>>>(ps, x, Wl1, Wr1, bl1, ph1, NODES1);
    score_kernel<<<(NODES1 * 32) / 256, 256>>>(ph1, pw1, psc1, NODES1);
    topk_kernel<<<B_, 1024>>>(psc1, pperm1, pinv1, N_, K1_);
    gate_kernel<<<(NODES2 * 32) / 256, 256>>>(ph1, psc1, pperm1, ph1p, NODES2);
    readout_kernel<<<B_, 512>>>(ph1p, px1, K1_);

    // ---- layer 2 ----
    agg2_kernel<<<(E_ * 32) / 256, 256>>>(ph1p, src, dst, pinv1, ps2, pcnt2);
    meandiv_kernel<<<(NODES2 * 32) / 256, 256>>>(ps2, pcnt2, NODES2);
    sage_gemm_kernel<<<NODES2 / 64, 256>>>(ps2, ph1p, Wl2, Wr2, bl2, ph2, NODES2);
    score_kernel<<<(NODES2 * 32) / 256, 256>>>(ph2, pw2, psc2, NODES2);
    topk_kernel<<<B_, 1024>>>(psc2, pperm2, (int*)0, K1_, K2_);
    gate_kernel<<<(NODES3 * 32) / 256, 256>>>(ph2, psc2, pperm2, ph2p, NODES3);
    readout_kernel<<<B_, 512>>>(ph2p, px2, K2_);

    // ---- head ----
    mlp_kernel<<<B_, 128>>>(px1, px2, fW1, fb1, fW2, fb2, out);
}

// round 12
// speedup vs baseline: 1.2641x; 1.2525x over previous
#include <cuda_runtime.h>
#include <cuda_bf16.h>
#include <mma.h>
#include <math.h>
#include <stdint.h>

using namespace nvcuda;

// ---------------- Fixed problem geometry ----------------
#define B_      64
#define N_      1024
#define E_      655360
#define H_      128
#define K1_     820
#define K2_     656
#define NODES1  (B_ * N_)    // 65536
#define NODES2  (B_ * K1_)   // 52480
#define NODES3  (B_ * K2_)   // 41984

// ---------------- Scratch (static device globals; no runtime alloc) ----------------
__device__ float g_s     [NODES1 * 128];
__device__ float g_cnt   [NODES1];
__device__ float g_h1    [NODES1 * 128];
__device__ float g_score1[NODES1];
__device__ int   g_perm1 [NODES2];
__device__ int   g_inv1  [NODES1];
__device__ float g_h1p   [NODES2 * 128];
__device__ float g_x1    [B_ * 256];
__device__ float g_s2    [NODES2 * 128];
__device__ float g_cnt2  [NODES2];
__device__ float g_h2    [NODES2 * 128];
__device__ float g_score2[NODES2];
__device__ int   g_perm2 [NODES3];
__device__ float g_h2p   [NODES3 * 128];
__device__ float g_x2    [B_ * 256];
// transposed, bf16-split weights: [n=128][k=256] K-major (k contiguous)
__device__ __nv_bfloat16 g_wthi1[128 * 256];
__device__ __nv_bfloat16 g_wtlo1[128 * 256];
__device__ __nv_bfloat16 g_wthi2[128 * 256];
__device__ __nv_bfloat16 g_wtlo2[128 * 256];

// ---------------- Edge aggregation (layer 1): s[dst] += x[src], cnt[dst] += 1 ----------------
__global__ void agg1_kernel(const float* __restrict__ x,
                            const int* __restrict__ src, const int* __restrict__ dst,
                            float* __restrict__ s, float* __restrict__ cnt)
{
    int g = blockIdx.x * blockDim.x + threadIdx.x;
    int e = g >> 5, lane = g & 31;
    if (e >= E_) return;
    int sn = src[e], dn = dst[e];
    float4 v = ((const float4*)(x + (size_t)sn * 128))[lane];
    atomicAdd(((float4*)(s + (size_t)dn * 128)) + lane, v);
    if (lane == 0) atomicAdd(cnt + dn, 1.0f);
}

// ---------------- Edge aggregation (layer 2) through inv-relabel; drop masked edges ------------
__global__ void agg2_kernel(const float* __restrict__ h1p,
                            const int* __restrict__ src, const int* __restrict__ dst,
                            const int* __restrict__ inv,
                            float* __restrict__ s2, float* __restrict__ cnt2)
{
    int g = blockIdx.x * blockDim.x + threadIdx.x;
    int e = g >> 5, lane = g & 31;
    if (e >= E_) return;
    int ns = inv[src[e]];
    int nd = inv[dst[e]];
    if (ns < 0 || nd < 0) return;
    float4 v = ((const float4*)(h1p + (size_t)ns * 128))[lane];
    atomicAdd(((float4*)(s2 + (size_t)nd * 128)) + lane, v);
    if (lane == 0) atomicAdd(cnt2 + nd, 1.0f);
}

// ---------------- mean: s[i][:] /= max(cnt[i],1), in place ------------------------------------
__global__ void meandiv_kernel(float* __restrict__ s, const float* __restrict__ cnt, int nrows)
{
    int i = blockIdx.x * blockDim.x + threadIdx.x;
    if (i >= nrows * 32) return;
    float c = fmaxf(cnt[i >> 5], 1.0f);
    float4 v = ((const float4*)s)[i];
    v.x /= c; v.y /= c; v.z /= c; v.w /= c;
    ((float4*)s)[i] = v;
}

// ---------------- weight prep: Wt_hi/lo[n][k] = split(W[k][n]), [Wl;Wr] stacked ---------------
__global__ void prep_w_kernel(const float* __restrict__ Wl, const float* __restrict__ Wr,
                              __nv_bfloat16* __restrict__ hi, __nv_bfloat16* __restrict__ lo)
{
    int i = blockIdx.x * blockDim.x + threadIdx.x;  // 128*256
    if (i >= 128 * 256) return;
    int n = i >> 8, k = i & 255;
    float v = (k < 128) ? Wl[k * 128 + n] : Wr[(k - 128) * 128 + n];
    __nv_bfloat16 h = __float2bfloat16(v);
    hi[i] = h;
    lo[i] = __float2bfloat16(v - __bfloat162float(h));
}

// ---------------- wmma bf16 SAGE GEMM: out = relu([mean|xin] @ [Wl;Wr] + bias) ---------------
// 128x128 tile/CTA, 8 warps (4x2 grid of 32x64 warp tiles), K=256 in 4 chunks of 64.
// Split-bf16 3-product fp32 emulation: Ahi*Bhi + Ahi*Blo + Alo*Bhi, fp32 accumulators.
#define LDA     72                       // padded k-stride (elements) for A/B SMEM tiles
#define SM_BIAS 0                        // 128 floats
#define SM_AHI  1024
#define SM_ALO  (SM_AHI + 128 * LDA * 2)     // +18432
#define SM_BHI  (SM_ALO + 128 * LDA * 2)
#define SM_BLO  (SM_BHI + 128 * LDA * 2)
#define SM_END  (SM_BLO + 128 * LDA * 2)     // 1024 + 73728 = 74752
#define SM_OUT  1024                     // reused: 128 x 132 f32 = 67584
#define LDO     132

__global__ __launch_bounds__(256, 2)
void sage_wmma_kernel(const float* __restrict__ mean, const float* __restrict__ xin,
                      const __nv_bfloat16* __restrict__ wt_hi,
                      const __nv_bfloat16* __restrict__ wt_lo,
                      const float* __restrict__ bias, float* __restrict__ outp)
{
    extern __shared__ char smem[];
    float* sbias = (float*)(smem + SM_BIAS);
    __nv_bfloat16* sAhi = (__nv_bfloat16*)(smem + SM_AHI);
    __nv_bfloat16* sAlo = (__nv_bfloat16*)(smem + SM_ALO);
    __nv_bfloat16* sBhi = (__nv_bfloat16*)(smem + SM_BHI);
    __nv_bfloat16* sBlo = (__nv_bfloat16*)(smem + SM_BLO);

    int tid = threadIdx.x;
    int warp = tid >> 5;
    int wy = warp >> 1;          // 0..3 -> rows wy*32
    int wx = warp & 1;           // 0..1 -> cols wx*64
    int row0 = blockIdx.x * 128;

    if (tid < 128) sbias[tid] = bias[tid];

    wmma::fragment<wmma::accumulator, 16, 16, 16, float> acc[2][4];
    #pragma unroll
    for (int mi = 0; mi < 2; mi++)
        #pragma unroll
        for (int nt = 0; nt < 4; nt++) wmma::fill_fragment(acc[mi][nt], 0.0f);

    #pragma unroll 1
    for (int chunk = 0; chunk < 4; chunk++) {
        // ---- stage A chunk [128 rows x 64 k]: fp32 -> bf16 hi/lo ----
        const float* abase = (chunk < 2) ? mean : xin;
        int acol = (chunk & 1) * 64;
        #pragma unroll
        for (int s = tid; s < 1024; s += 256) {
            int r = s >> 3, kseg = s & 7;
            const float* ap = abase + (size_t)(row0 + r) * 128 + acol + kseg * 8;
            float4 v0 = *(const float4*)ap;
            float4 v1 = *(const float4*)(ap + 4);
            float vv[8] = {v0.x, v0.y, v0.z, v0.w, v1.x, v1.y, v1.z, v1.w};
            unsigned int Hh[4], Ll[4];
            #pragma unroll
            for (int i = 0; i < 4; i++) {
                __nv_bfloat16 h0 = __float2bfloat16(vv[2 * i]);
                __nv_bfloat16 h1 = __float2bfloat16(vv[2 * i + 1]);
                __nv_bfloat16 l0 = __float2bfloat16(vv[2 * i] - __bfloat162float(h0));
                __nv_bfloat16 l1 = __float2bfloat16(vv[2 * i + 1] - __bfloat162float(h1));
                Hh[i] = (unsigned int)__bfloat16_as_ushort(h0)
                      | ((unsigned int)__bfloat16_as_ushort(h1) << 16);
                Ll[i] = (unsigned int)__bfloat16_as_ushort(l0)
                      | ((unsigned int)__bfloat16_as_ushort(l1) << 16);
            }
            *(uint4*)(sAhi + r * LDA + kseg * 8) = make_uint4(Hh[0], Hh[1], Hh[2], Hh[3]);
            *(uint4*)(sAlo + r * LDA + kseg * 8) = make_uint4(Ll[0], Ll[1], Ll[2], Ll[3]);
        }
        // ---- stage B chunk [128 n x 64 k] from pre-split K-major weights ----
        #pragma unroll
        for (int s = tid; s < 1024; s += 256) {
            int n = s >> 3, kseg = s & 7;
            size_t gi = (size_t)n * 256 + chunk * 64 + kseg * 8;
            *(uint4*)(sBhi + n * LDA + kseg * 8) = *(const uint4*)(wt_hi + gi);
            *(uint4*)(sBlo + n * LDA + kseg * 8) = *(const uint4*)(wt_lo + gi);
        }
        __syncthreads();

        // ---- compute: 4 k16-steps, warp tile 32x64 = 2x4 wmma tiles, 3 products ----
        #pragma unroll
        for (int ks = 0; ks < 4; ks++) {
            wmma::fragment<wmma::matrix_a, 16, 16, 16, __nv_bfloat16, wmma::row_major> ahi[2], alo[2];
            #pragma unroll
            for (int mi = 0; mi < 2; mi++) {
                const __nv_bfloat16* ap = sAhi + (wy * 32 + mi * 16) * LDA + ks * 16;
                const __nv_bfloat16* lp = sAlo + (wy * 32 + mi * 16) * LDA + ks * 16;
                wmma::load_matrix_sync(ahi[mi], ap, LDA);
                wmma::load_matrix_sync(alo[mi], lp, LDA);
            }
            #pragma unroll
            for (int nt = 0; nt < 4; nt++) {
                // matrix_b col_major: element (k, n) at ptr[n*ldm + k] == Bt[n][k]
                wmma::fragment<wmma::matrix_b, 16, 16, 16, __nv_bfloat16, wmma::col_major> bhi, blo;
                const __nv_bfloat16* bp = sBhi + (wx * 64 + nt * 16) * LDA + ks * 16;
                const __nv_bfloat16* cp = sBlo + (wx * 64 + nt * 16) * LDA + ks * 16;
                wmma::load_matrix_sync(bhi, bp, LDA);
                wmma::load_matrix_sync(blo, cp, LDA);
                #pragma unroll
                for (int mi = 0; mi < 2; mi++) {
                    wmma::mma_sync(acc[mi][nt], ahi[mi], bhi, acc[mi][nt]);
                    wmma::mma_sync(acc[mi][nt], ahi[mi], blo, acc[mi][nt]);
                    wmma::mma_sync(acc[mi][nt], alo[mi], bhi, acc[mi][nt]);
                }
            }
        }
        __syncthreads();
    }

    // ---- epilogue: dump accs to SMEM, bias+relu, vectorized store ----
    float* sout = (float*)(smem + SM_OUT);
    #pragma unroll
    for (int mi = 0; mi < 2; mi++)
        #pragma unroll
        for (int nt = 0; nt < 4; nt++)
            wmma::store_matrix_sync(sout + (wy * 32 + mi * 16) * LDO + wx * 64 + nt * 16,
                                    acc[mi][nt], LDO, wmma::mem_row_major);
    __syncthreads();

    // 128x128 floats, 256 threads -> each thread 16 float4s (two rows of 8)
    int tr = tid >> 1;                  // 0..127 row pairs base
    int tc = (tid & 1) * 64;            // half-row
    #pragma unroll
    for (int q = 0; q < 16; q++) {
        int col = tc + q * 4;
        float4 v = *(float4*)&sout[tr * LDO + col];
        float4 bb = *(float4*)&sbias[col];
        v.x = fmaxf(v.x + bb.x, 0.0f);
        v.y = fmaxf(v.y + bb.y, 0.0f);
        v.z = fmaxf(v.z + bb.z, 0.0f);
        v.w = fmaxf(v.w + bb.w, 0.0f);
        *(float4*)&outp[(size_t)(row0 + tr) * 128 + col] = v;
    }
}

// ---------------- score = tanh(h . w / ||w||), one warp per node -----------------------------
__global__ void score_kernel(const float* __restrict__ h, const float* __restrict__ w,
                             float* __restrict__ score, int n)
{
    int g = blockIdx.x * blockDim.x + threadIdx.x;
    int node = g >> 5, lane = g & 31;
    if (node >= n) return;
    float4 wv = ((const float4*)w)[lane];
    float4 hv = ((const float4*)(h + (size_t)node * 128))[lane];
    float d  = hv.x * wv.x + hv.y * wv.y + hv.z * wv.z + hv.w * wv.w;
    float nw = wv.x * wv.x + wv.y * wv.y + wv.z * wv.z + wv.w * wv.w;
    #pragma unroll
    for (int o = 16; o; o >>= 1) {
        d  += __shfl_xor_sync(0xFFFFFFFFu, d, o);
        nw += __shfl_xor_sync(0xFFFFFFFFu, nw, o);
    }
    if (lane == 0) score[node] = tanhf(d * rsqrtf(nw));
}

// ---------------- TopK pool: per-graph bitonic sort (desc score, asc idx), compact by idx ----
__global__ __launch_bounds__(1024) void topk_kernel(
    const float* __restrict__ score, int* __restrict__ perm, int* __restrict__ inv,
    int n_per, int K)
{
    __shared__ unsigned long long keys[1024];
    __shared__ int keep[1024];
    __shared__ int scan[1024];
    int tid = threadIdx.x, b = blockIdx.x;

    float sc = (tid < n_per) ? score[b * n_per + tid] : __int_as_float(0xFF800000);
    unsigned int bits = __float_as_uint(sc);
    unsigned int u = (bits & 0x80000000u) ? ~bits : (bits | 0x80000000u);
    keys[tid] = ((unsigned long long)u << 32) | (unsigned int)(1023 - tid);
    keep[tid] = 0;
    __syncthreads();

    for (int k = 2; k <= 1024; k <<= 1) {
        for (int j = k >> 1; j > 0; j >>= 1) {
            int ixj = tid ^ j;
            if (ixj > tid) {
                unsigned long long a = keys[tid], c = keys[ixj];
                bool up = ((tid & k) == 0);
                bool sw = up ? (a < c) : (a > c);
                if (sw) { keys[tid] = c; keys[ixj] = a; }
            }
            __syncthreads();
        }
    }

    if (tid < K) {
        int idx = 1023 - (int)(keys[tid] & 0xFFFFFFFFu);
        keep[idx] = 1;
    }
    __syncthreads();

    int v = keep[tid];
    scan[tid] = v;
    __syncthreads();
    for (int off = 1; off < 1024; off <<= 1) {
        int t = (tid >= off) ? scan[tid - off] : 0;
        __syncthreads();
        scan[tid] += t;
        __syncthreads();
    }

    if (tid < n_per) {
        int old = b * n_per + tid;
        if (v) {
            int newid = b * K + (scan[tid] - 1);
            perm[newid] = old;
            if (inv) inv[old] = newid;
        } else if (inv) {
            inv[old] = -1;
        }
    }
}

// ---------------- gate: hp[new] = h[perm[new]] * score[perm[new]] -----------------------------
__global__ void gate_kernel(const float* __restrict__ h, const float* __restrict__ score,
                            const int* __restrict__ perm, float* __restrict__ hp, int total)
{
    int g = blockIdx.x * blockDim.x + threadIdx.x;
    int nid = g >> 5, lane = g & 31;
    if (nid >= total) return;
    int old = perm[nid];
    float sc = score[old];
    float4 v = ((const float4*)(h + (size_t)old * 128))[lane];
    v.x *= sc; v.y *= sc; v.z *= sc; v.w *= sc;
    ((float4*)(hp + (size_t)nid * 128))[lane] = v;
}

// ---------------- readout: [mean over K | max over K] per graph ------------------------------
__global__ void readout_kernel(const float* __restrict__ hp, float* __restrict__ xout, int K)
{
    __shared__ float ss[4][128], sm[4][128];
    int b = blockIdx.x;
    int tid = threadIdx.x;          // 512 threads
    int f = tid & 127, ty = tid >> 7;
    float sum = 0.0f, mx = __int_as_float(0xFF800000);
    for (int r = ty; r < K; r += 4) {
        float v = hp[((size_t)(b * K + r)) * 128 + f];
        sum += v;
        mx = fmaxf(mx, v);
    }
    ss[ty][f] = sum; sm[ty][f] = mx;
    __syncthreads();
    if (ty == 0) {
        float s = ss[0][f] + ss[1][f] + ss[2][f] + ss[3][f];
        float m = fmaxf(fmaxf(sm[0][f], sm[1][f]), fmaxf(sm[2][f], sm[3][f]));
        xout[b * 256 + f] = s / (float)K;
        xout[b * 256 + 128 + f] = m;
    }
}

// ---------------- final MLP: out = relu((x1+x2)@fW1+fb1) @ fW2 + fb2 --------------------------
__global__ void mlp_kernel(const float* __restrict__ x1, const float* __restrict__ x2,
                           const float* __restrict__ fW1, const float* __restrict__ fb1,
                           const float* __restrict__ fW2, const float* __restrict__ fb2,
                           float* __restrict__ out)
{
    __shared__ float row[256];
    __shared__ float zs[128];
    int b = blockIdx.x, t = threadIdx.x;
    row[t]       = x1[b * 256 + t]       + x2[b * 256 + t];
    row[t + 128] = x1[b * 256 + 128 + t] + x2[b * 256 + 128 + t];
    __syncthreads();
    float acc = fb1[t];
    #pragma unroll 8
    for (int k = 0; k < 256; k++) acc += row[k] * fW1[k * 128 + t];
    zs[t] = fmaxf(acc, 0.0f);
    __syncthreads();
    if (t < 10) {
        float o = fb2[t];
        #pragma unroll 8
        for (int k = 0; k < 128; k++) o += zs[k] * fW2[k * 10 + t];
        out[b * 10 + t] = o;
    }
}

// ---------------- host orchestration ----------------------------------------------------------
extern "C" void kernel_launch(void* const* d_in, const int* in_sizes, int n_in,
                              void* d_out, int out_size)
{
    (void)in_sizes; (void)n_in; (void)out_size;
    const float* x   = (const float*)d_in[0];
    const int*   ei  = (const int*)d_in[1];
    const float* Wl1 = (const float*)d_in[3];
    const float* bl1 = (const float*)d_in[4];
    const float* Wr1 = (const float*)d_in[5];
    const float* Wl2 = (const float*)d_in[6];
    const float* bl2 = (const float*)d_in[7];
    const float* Wr2 = (const float*)d_in[8];
    const float* pw1 = (const float*)d_in[9];
    const float* pw2 = (const float*)d_in[10];
    const float* fW1 = (const float*)d_in[11];
    const float* fb1 = (const float*)d_in[12];
    const float* fW2 = (const float*)d_in[13];
    const float* fb2 = (const float*)d_in[14];
    float* out = (float*)d_out;

    const int* src = ei;
    const int* dst = ei + E_;

    float *ps, *pcnt, *ph1, *psc1, *ph1p, *px1, *ps2, *pcnt2, *ph2, *psc2, *ph2p, *px2;
    int *pperm1, *pinv1, *pperm2;
    __nv_bfloat16 *pwh1, *pwl1_, *pwh2, *pwl2_;
    cudaGetSymbolAddress((void**)&ps,     g_s);
    cudaGetSymbolAddress((void**)&pcnt,   g_cnt);
    cudaGetSymbolAddress((void**)&ph1,    g_h1);
    cudaGetSymbolAddress((void**)&psc1,   g_score1);
    cudaGetSymbolAddress((void**)&pperm1, g_perm1);
    cudaGetSymbolAddress((void**)&pinv1,  g_inv1);
    cudaGetSymbolAddress((void**)&ph1p,   g_h1p);
    cudaGetSymbolAddress((void**)&px1,    g_x1);
    cudaGetSymbolAddress((void**)&ps2,    g_s2);
    cudaGetSymbolAddress((void**)&pcnt2,  g_cnt2);
    cudaGetSymbolAddress((void**)&ph2,    g_h2);
    cudaGetSymbolAddress((void**)&psc2,   g_score2);
    cudaGetSymbolAddress((void**)&pperm2, g_perm2);
    cudaGetSymbolAddress((void**)&ph2p,   g_h2p);
    cudaGetSymbolAddress((void**)&px2,    g_x2);
    cudaGetSymbolAddress((void**)&pwh1,   g_wthi1);
    cudaGetSymbolAddress((void**)&pwl1_,  g_wtlo1);
    cudaGetSymbolAddress((void**)&pwh2,   g_wthi2);
    cudaGetSymbolAddress((void**)&pwl2_,  g_wtlo2);

    cudaFuncSetAttribute(sage_wmma_kernel,
                         cudaFuncAttributeMaxDynamicSharedMemorySize, SM_END);

    // zero accumulators
    cudaMemsetAsync(ps,    0, sizeof(float) * NODES1 * 128);
    cudaMemsetAsync(pcnt,  0, sizeof(float) * NODES1);
    cudaMemsetAsync(ps2,   0, sizeof(float) * NODES2 * 128);
    cudaMemsetAsync(pcnt2, 0, sizeof(float) * NODES2);

    // weight prep
    prep_w_kernel<<<128, 256>>>(Wl1, Wr1, pwh1, pwl1_);
    prep_w_kernel<<<128, 256>>>(Wl2, Wr2, pwh2, pwl2_);

    // ---- layer 1 ----
    agg1_kernel<<<(E_ * 32) / 256, 256>>>(x, src, dst, ps, pcnt);
    meandiv_kernel<<<(NODES1 * 32) / 256, 256>>>(ps, pcnt, NODES1);
    sage_wmma_kernel<<<NODES1 / 128, 256, SM_END>>>(ps, x, pwh1, pwl1_, bl1, ph1);
    score_kernel<<<(NODES1 * 32) / 256, 256>>>(ph1, pw1, psc1, NODES1);
    topk_kernel<<<B_, 1024>>>(psc1, pperm1, pinv1, N_, K1_);
    gate_kernel<<<(NODES2 * 32) / 256, 256>>>(ph1, psc1, pperm1, ph1p, NODES2);
    readout_kernel<<<B_, 512>>>(ph1p, px1, K1_);

    // ---- layer 2 ----
    agg2_kernel<<<(E_ * 32) / 256, 256>>>(ph1p, src, dst, pinv1, ps2, pcnt2);
    meandiv_kernel<<<(NODES2 * 32) / 256, 256>>>(ps2, pcnt2, NODES2);
    sage_wmma_kernel<<<NODES2 / 128, 256, SM_END>>>(ps2, ph1p, pwh2, pwl2_, bl2, ph2);
    score_kernel<<<(NODES2 * 32) / 256, 256>>>(ph2, pw2, psc2, NODES2);
    topk_kernel<<<B_, 1024>>>(psc2, pperm2, (int*)0, K1_, K2_);
    gate_kernel<<<(NODES3 * 32) / 256, 256>>>(ph2, psc2, pperm2, ph2p, NODES3);
    readout_kernel<<<B_, 512>>>(ph2p, px2, K2_);

    // ---- head ----
    mlp_kernel<<<B_, 128>>>(px1, px2, fW1, fb1, fW2, fb2, out);
}

// round 13
// speedup vs baseline: 1.2668x; 1.0022x over previous
#include <cuda_runtime.h>
#include <cuda_bf16.h>
#include <mma.h>
#include <math.h>
#include <stdint.h>

using namespace nvcuda;

// ---------------- Fixed problem geometry ----------------
#define B_      64
#define N_      1024
#define E_      655360
#define H_      128
#define K1_     820
#define K2_     656
#define NODES1  (B_ * N_)    // 65536
#define NODES2  (B_ * K1_)   // 52480
#define NODES3  (B_ * K2_)   // 41984

// ---------------- Scratch (static device globals; no runtime alloc) ----------------
__device__ float g_s     [NODES1 * 128];
__device__ float g_cnt   [NODES1];
__device__ float g_h1    [NODES1 * 128];
__device__ float g_score1[NODES1];
__device__ int   g_perm1 [NODES2];
__device__ int   g_inv1  [NODES1];
__device__ float g_h1p   [NODES2 * 128];
__device__ float g_x1    [B_ * 256];
__device__ float g_s2    [NODES2 * 128];
__device__ float g_cnt2  [NODES2];
__device__ float g_h2    [NODES2 * 128];
__device__ float g_score2[NODES2];
__device__ int   g_perm2 [NODES3];
__device__ float g_h2p   [NODES3 * 128];
__device__ float g_x2    [B_ * 256];
// transposed, bf16-split weights: [n=128][k=256] K-major (k contiguous)
__device__ __nv_bfloat16 g_wthi1[128 * 256];
__device__ __nv_bfloat16 g_wtlo1[128 * 256];
__device__ __nv_bfloat16 g_wthi2[128 * 256];
__device__ __nv_bfloat16 g_wtlo2[128 * 256];

// ---------------- Edge aggregation (layer 1): s[dst] += x[src], cnt[dst] += 1 ----------------
__global__ void agg1_kernel(const float* __restrict__ x,
                            const int* __restrict__ src, const int* __restrict__ dst,
                            float* __restrict__ s, float* __restrict__ cnt)
{
    int g = blockIdx.x * blockDim.x + threadIdx.x;
    int e = g >> 5, lane = g & 31;
    if (e >= E_) return;
    int sn = src[e], dn = dst[e];
    float4 v = ((const float4*)(x + (size_t)sn * 128))[lane];
    atomicAdd(((float4*)(s + (size_t)dn * 128)) + lane, v);
    if (lane == 0) atomicAdd(cnt + dn, 1.0f);
}

// ---------------- Edge aggregation (layer 2) through inv-relabel; drop masked edges ------------
__global__ void agg2_kernel(const float* __restrict__ h1p,
                            const int* __restrict__ src, const int* __restrict__ dst,
                            const int* __restrict__ inv,
                            float* __restrict__ s2, float* __restrict__ cnt2)
{
    int g = blockIdx.x * blockDim.x + threadIdx.x;
    int e = g >> 5, lane = g & 31;
    if (e >= E_) return;
    int ns = inv[src[e]];
    int nd = inv[dst[e]];
    if (ns < 0 || nd < 0) return;
    float4 v = ((const float4*)(h1p + (size_t)ns * 128))[lane];
    atomicAdd(((float4*)(s2 + (size_t)nd * 128)) + lane, v);
    if (lane == 0) atomicAdd(cnt2 + nd, 1.0f);
}

// ---------------- mean: s[i][:] /= max(cnt[i],1), in place ------------------------------------
__global__ void meandiv_kernel(float* __restrict__ s, const float* __restrict__ cnt, int nrows)
{
    int i = blockIdx.x * blockDim.x + threadIdx.x;
    if (i >= nrows * 32) return;
    float c = fmaxf(cnt[i >> 5], 1.0f);
    float4 v = ((const float4*)s)[i];
    v.x /= c; v.y /= c; v.z /= c; v.w /= c;
    ((float4*)s)[i] = v;
}

// ---------------- weight prep: Wt_hi/lo[n][k] = split(W[k][n]), [Wl;Wr] stacked ---------------
__global__ void prep_w_kernel(const float* __restrict__ Wl, const float* __restrict__ Wr,
                              __nv_bfloat16* __restrict__ hi, __nv_bfloat16* __restrict__ lo)
{
    int i = blockIdx.x * blockDim.x + threadIdx.x;  // 128*256
    if (i >= 128 * 256) return;
    int n = i >> 8, k = i & 255;
    float v = (k < 128) ? Wl[k * 128 + n] : Wr[(k - 128) * 128 + n];
    __nv_bfloat16 h = __float2bfloat16(v);
    hi[i] = h;
    lo[i] = __float2bfloat16(v - __bfloat162float(h));
}

// ---------------- wmma bf16 SAGE GEMM: out = relu([mean|xin] @ [Wl;Wr] + bias) ---------------
// 128x128 tile/CTA, 8 warps (4x2 grid of 32x64 warp tiles), K=256 in 4 chunks of 64.
// Split-bf16 3-product fp32 emulation: Ahi*Bhi + Ahi*Blo + Alo*Bhi, fp32 accumulators.
#define LDA     72                       // padded k-stride (elements) for A/B SMEM tiles
#define SM_BIAS 0                        // 128 floats
#define SM_AHI  1024
#define SM_ALO  (SM_AHI + 128 * LDA * 2)     // +18432
#define SM_BHI  (SM_ALO + 128 * LDA * 2)
#define SM_BLO  (SM_BHI + 128 * LDA * 2)
#define SM_END  (SM_BLO + 128 * LDA * 2)     // 1024 + 73728 = 74752
#define SM_OUT  1024                     // reused: 128 x 132 f32 = 67584
#define LDO     132

__global__ __launch_bounds__(256, 2)
void sage_wmma_kernel(const float* __restrict__ mean, const float* __restrict__ xin,
                      const __nv_bfloat16* __restrict__ wt_hi,
                      const __nv_bfloat16* __restrict__ wt_lo,
                      const float* __restrict__ bias, float* __restrict__ outp)
{
    extern __shared__ char smem[];
    float* sbias = (float*)(smem + SM_BIAS);
    __nv_bfloat16* sAhi = (__nv_bfloat16*)(smem + SM_AHI);
    __nv_bfloat16* sAlo = (__nv_bfloat16*)(smem + SM_ALO);
    __nv_bfloat16* sBhi = (__nv_bfloat16*)(smem + SM_BHI);
    __nv_bfloat16* sBlo = (__nv_bfloat16*)(smem + SM_BLO);

    int tid = threadIdx.x;
    int warp = tid >> 5;
    int wy = warp >> 1;          // 0..3 -> rows wy*32
    int wx = warp & 1;           // 0..1 -> cols wx*64
    int row0 = blockIdx.x * 128;

    if (tid < 128) sbias[tid] = bias[tid];

    wmma::fragment<wmma::accumulator, 16, 16, 16, float> acc[2][4];
    #pragma unroll
    for (int mi = 0; mi < 2; mi++)
        #pragma unroll
        for (int nt = 0; nt < 4; nt++) wmma::fill_fragment(acc[mi][nt], 0.0f);

    #pragma unroll 1
    for (int chunk = 0; chunk < 4; chunk++) {
        // ---- stage A chunk [128 rows x 64 k]: fp32 -> bf16 hi/lo ----
        const float* abase = (chunk < 2) ? mean : xin;
        int acol = (chunk & 1) * 64;
        #pragma unroll
        for (int s = tid; s < 1024; s += 256) {
            int r = s >> 3, kseg = s & 7;
            const float* ap = abase + (size_t)(row0 + r) * 128 + acol + kseg * 8;
            float4 v0 = *(const float4*)ap;
            float4 v1 = *(const float4*)(ap + 4);
            float vv[8] = {v0.x, v0.y, v0.z, v0.w, v1.x, v1.y, v1.z, v1.w};
            unsigned int Hh[4], Ll[4];
            #pragma unroll
            for (int i = 0; i < 4; i++) {
                __nv_bfloat16 h0 = __float2bfloat16(vv[2 * i]);
                __nv_bfloat16 h1 = __float2bfloat16(vv[2 * i + 1]);
                __nv_bfloat16 l0 = __float2bfloat16(vv[2 * i] - __bfloat162float(h0));
                __nv_bfloat16 l1 = __float2bfloat16(vv[2 * i + 1] - __bfloat162float(h1));
                Hh[i] = (unsigned int)__bfloat16_as_ushort(h0)
                      | ((unsigned int)__bfloat16_as_ushort(h1) << 16);
                Ll[i] = (unsigned int)__bfloat16_as_ushort(l0)
                      | ((unsigned int)__bfloat16_as_ushort(l1) << 16);
            }
            *(uint4*)(sAhi + r * LDA + kseg * 8) = make_uint4(Hh[0], Hh[1], Hh[2], Hh[3]);
            *(uint4*)(sAlo + r * LDA + kseg * 8) = make_uint4(Ll[0], Ll[1], Ll[2], Ll[3]);
        }
        // ---- stage B chunk [128 n x 64 k] from pre-split K-major weights ----
        #pragma unroll
        for (int s = tid; s < 1024; s += 256) {
            int n = s >> 3, kseg = s & 7;
            size_t gi = (size_t)n * 256 + chunk * 64 + kseg * 8;
            *(uint4*)(sBhi + n * LDA + kseg * 8) = *(const uint4*)(wt_hi + gi);
            *(uint4*)(sBlo + n * LDA + kseg * 8) = *(const uint4*)(wt_lo + gi);
        }
        __syncthreads();

        // ---- compute: 4 k16-steps, warp tile 32x64 = 2x4 wmma tiles, 3 products ----
        #pragma unroll
        for (int ks = 0; ks < 4; ks++) {
            wmma::fragment<wmma::matrix_a, 16, 16, 16, __nv_bfloat16, wmma::row_major> ahi[2], alo[2];
            #pragma unroll
            for (int mi = 0; mi < 2; mi++) {
                const __nv_bfloat16* ap = sAhi + (wy * 32 + mi * 16) * LDA + ks * 16;
                const __nv_bfloat16* lp = sAlo + (wy * 32 + mi * 16) * LDA + ks * 16;
                wmma::load_matrix_sync(ahi[mi], ap, LDA);
                wmma::load_matrix_sync(alo[mi], lp, LDA);
            }
            #pragma unroll
            for (int nt = 0; nt < 4; nt++) {
                // matrix_b col_major: element (k, n) at ptr[n*ldm + k] == Bt[n][k]
                wmma::fragment<wmma::matrix_b, 16, 16, 16, __nv_bfloat16, wmma::col_major> bhi, blo;
                const __nv_bfloat16* bp = sBhi + (wx * 64 + nt * 16) * LDA + ks * 16;
                const __nv_bfloat16* cp = sBlo + (wx * 64 + nt * 16) * LDA + ks * 16;
                wmma::load_matrix_sync(bhi, bp, LDA);
                wmma::load_matrix_sync(blo, cp, LDA);
                #pragma unroll
                for (int mi = 0; mi < 2; mi++) {
                    wmma::mma_sync(acc[mi][nt], ahi[mi], bhi, acc[mi][nt]);
                    wmma::mma_sync(acc[mi][nt], ahi[mi], blo, acc[mi][nt]);
                    wmma::mma_sync(acc[mi][nt], alo[mi], bhi, acc[mi][nt]);
                }
            }
        }
        __syncthreads();
    }

    // ---- epilogue: dump accs to SMEM, bias+relu, vectorized store ----
    float* sout = (float*)(smem + SM_OUT);
    #pragma unroll
    for (int mi = 0; mi < 2; mi++)
        #pragma unroll
        for (int nt = 0; nt < 4; nt++)
            wmma::store_matrix_sync(sout + (wy * 32 + mi * 16) * LDO + wx * 64 + nt * 16,
                                    acc[mi][nt], LDO, wmma::mem_row_major);
    __syncthreads();

    // 128x128 floats, 256 threads -> each thread 16 float4s (two rows of 8)
    int tr = tid >> 1;                  // 0..127 row pairs base
    int tc = (tid & 1) * 64;            // half-row
    #pragma unroll
    for (int q = 0; q < 16; q++) {
        int col = tc + q * 4;
        float4 v = *(float4*)&sout[tr * LDO + col];
        float4 bb = *(float4*)&sbias[col];
        v.x = fmaxf(v.x + bb.x, 0.0f);
        v.y = fmaxf(v.y + bb.y, 0.0f);
        v.z = fmaxf(v.z + bb.z, 0.0f);
        v.w = fmaxf(v.w + bb.w, 0.0f);
        *(float4*)&outp[(size_t)(row0 + tr) * 128 + col] = v;
    }
}

// ---------------- score = tanh(h . w / ||w||), one warp per node -----------------------------
__global__ void score_kernel(const float* __restrict__ h, const float* __restrict__ w,
                             float* __restrict__ score, int n)
{
    int g = blockIdx.x * blockDim.x + threadIdx.x;
    int node = g >> 5, lane = g & 31;
    if (node >= n) return;
    float4 wv = ((const float4*)w)[lane];
    float4 hv = ((const float4*)(h + (size_t)node * 128))[lane];
    float d  = hv.x * wv.x + hv.y * wv.y + hv.z * wv.z + hv.w * wv.w;
    float nw = wv.x * wv.x + wv.y * wv.y + wv.z * wv.z + wv.w * wv.w;
    #pragma unroll
    for (int o = 16; o; o >>= 1) {
        d  += __shfl_xor_sync(0xFFFFFFFFu, d, o);
        nw += __shfl_xor_sync(0xFFFFFFFFu, nw, o);
    }
    if (lane == 0) score[node] = tanhf(d * rsqrtf(nw));
}

// ---------------- TopK pool: per-graph bitonic sort (desc score, asc idx), compact by idx ----
__global__ __launch_bounds__(1024) void topk_kernel(
    const float* __restrict__ score, int* __restrict__ perm, int* __restrict__ inv,
    int n_per, int K)
{
    __shared__ unsigned long long keys[1024];
    __shared__ int keep[1024];
    __shared__ int scan[1024];
    int tid = threadIdx.x, b = blockIdx.x;

    float sc = (tid < n_per) ? score[b * n_per + tid] : __int_as_float(0xFF800000);
    unsigned int bits = __float_as_uint(sc);
    unsigned int u = (bits & 0x80000000u) ? ~bits : (bits | 0x80000000u);
    keys[tid] = ((unsigned long long)u << 32) | (unsigned int)(1023 - tid);
    keep[tid] = 0;
    __syncthreads();

    for (int k = 2; k <= 1024; k <<= 1) {
        for (int j = k >> 1; j > 0; j >>= 1) {
            int ixj = tid ^ j;
            if (ixj > tid) {
                unsigned long long a = keys[tid], c = keys[ixj];
                bool up = ((tid & k) == 0);
                bool sw = up ? (a < c) : (a > c);
                if (sw) { keys[tid] = c; keys[ixj] = a; }
            }
            __syncthreads();
        }
    }

    if (tid < K) {
        int idx = 1023 - (int)(keys[tid] & 0xFFFFFFFFu);
        keep[idx] = 1;
    }
    __syncthreads();

    int v = keep[tid];
    scan[tid] = v;
    __syncthreads();
    for (int off = 1; off < 1024; off <<= 1) {
        int t = (tid >= off) ? scan[tid - off] : 0;
        __syncthreads();
        scan[tid] += t;
        __syncthreads();
    }

    if (tid < n_per) {
        int old = b * n_per + tid;
        if (v) {
            int newid = b * K + (scan[tid] - 1);
            perm[newid] = old;
            if (inv) inv[old] = newid;
        } else if (inv) {
            inv[old] = -1;
        }
    }
}

// ---------------- gate: hp[new] = h[perm[new]] * score[perm[new]] -----------------------------
__global__ void gate_kernel(const float* __restrict__ h, const float* __restrict__ score,
                            const int* __restrict__ perm, float* __restrict__ hp, int total)
{
    int g = blockIdx.x * blockDim.x + threadIdx.x;
    int nid = g >> 5, lane = g & 31;
    if (nid >= total) return;
    int old = perm[nid];
    float sc = score[old];
    float4 v = ((const float4*)(h + (size_t)old * 128))[lane];
    v.x *= sc; v.y *= sc; v.z *= sc; v.w *= sc;
    ((float4*)(hp + (size_t)nid * 128))[lane] = v;
}

// ---------------- readout: [mean over K | max over K] per graph ------------------------------
__global__ void readout_kernel(const float* __restrict__ hp, float* __restrict__ xout, int K)
{
    __shared__ float ss[4][128], sm[4][128];
    int b = blockIdx.x;
    int tid = threadIdx.x;          // 512 threads
    int f = tid & 127, ty = tid >> 7;
    float sum = 0.0f, mx = __int_as_float(0xFF800000);
    for (int r = ty; r < K; r += 4) {
        float v = hp[((size_t)(b * K + r)) * 128 + f];
        sum += v;
        mx = fmaxf(mx, v);
    }
    ss[ty][f] = sum; sm[ty][f] = mx;
    __syncthreads();
    if (ty == 0) {
        float s = ss[0][f] + ss[1][f] + ss[2][f] + ss[3][f];
        float m = fmaxf(fmaxf(sm[0][f], sm[1][f]), fmaxf(sm[2][f], sm[3][f]));
        xout[b * 256 + f] = s / (float)K;
        xout[b * 256 + 128 + f] = m;
    }
}

// ---------------- final MLP: out = relu((x1+x2)@fW1+fb1) @ fW2 + fb2 --------------------------
__global__ void mlp_kernel(const float* __restrict__ x1, const float* __restrict__ x2,
                           const float* __restrict__ fW1, const float* __restrict__ fb1,
                           const float* __restrict__ fW2, const float* __restrict__ fb2,
                           float* __restrict__ out)
{
    __shared__ float row[256];
    __shared__ float zs[128];
    int b = blockIdx.x, t = threadIdx.x;
    row[t]       = x1[b * 256 + t]       + x2[b * 256 + t];
    row[t + 128] = x1[b * 256 + 128 + t] + x2[b * 256 + 128 + t];
    __syncthreads();
    float acc = fb1[t];
    #pragma unroll 8
    for (int k = 0; k < 256; k++) acc += row[k] * fW1[k * 128 + t];
    zs[t] = fmaxf(acc, 0.0f);
    __syncthreads();
    if (t < 10) {
        float o = fb2[t];
        #pragma unroll 8
        for (int k = 0; k < 128; k++) o += zs[k] * fW2[k * 10 + t];
        out[b * 10 + t] = o;
    }
}

// ---------------- host orchestration ----------------------------------------------------------
extern "C" void kernel_launch(void* const* d_in, const int* in_sizes, int n_in,
                              void* d_out, int out_size)
{
    (void)in_sizes; (void)n_in; (void)out_size;
    const float* x   = (const float*)d_in[0];
    const int*   ei  = (const int*)d_in[1];
    const float* Wl1 = (const float*)d_in[3];
    const float* bl1 = (const float*)d_in[4];
    const float* Wr1 = (const float*)d_in[5];
    const float* Wl2 = (const float*)d_in[6];
    const float* bl2 = (const float*)d_in[7];
    const float* Wr2 = (const float*)d_in[8];
    const float* pw1 = (const float*)d_in[9];
    const float* pw2 = (const float*)d_in[10];
    const float* fW1 = (const float*)d_in[11];
    const float* fb1 = (const float*)d_in[12];
    const float* fW2 = (const float*)d_in[13];
    const float* fb2 = (const float*)d_in[14];
    float* out = (float*)d_out;

    const int* src = ei;
    const int* dst = ei + E_;

    float *ps, *pcnt, *ph1, *psc1, *ph1p, *px1, *ps2, *pcnt2, *ph2, *psc2, *ph2p, *px2;
    int *pperm1, *pinv1, *pperm2;
    __nv_bfloat16 *pwh1, *pwl1_, *pwh2, *pwl2_;
    cudaGetSymbolAddress((void**)&ps,     g_s);
    cudaGetSymbolAddress((void**)&pcnt,   g_cnt);
    cudaGetSymbolAddress((void**)&ph1,    g_h1);
    cudaGetSymbolAddress((void**)&psc1,   g_score1);
    cudaGetSymbolAddress((void**)&pperm1, g_perm1);
    cudaGetSymbolAddress((void**)&pinv1,  g_inv1);
    cudaGetSymbolAddress((void**)&ph1p,   g_h1p);
    cudaGetSymbolAddress((void**)&px1,    g_x1);
    cudaGetSymbolAddress((void**)&ps2,    g_s2);
    cudaGetSymbolAddress((void**)&pcnt2,  g_cnt2);
    cudaGetSymbolAddress((void**)&ph2,    g_h2);
    cudaGetSymbolAddress((void**)&psc2,   g_score2);
    cudaGetSymbolAddress((void**)&pperm2, g_perm2);
    cudaGetSymbolAddress((void**)&ph2p,   g_h2p);
    cudaGetSymbolAddress((void**)&px2,    g_x2);
    cudaGetSymbolAddress((void**)&pwh1,   g_wthi1);
    cudaGetSymbolAddress((void**)&pwl1_,  g_wtlo1);
    cudaGetSymbolAddress((void**)&pwh2,   g_wthi2);
    cudaGetSymbolAddress((void**)&pwl2_,  g_wtlo2);

    cudaFuncSetAttribute(sage_wmma_kernel,
                         cudaFuncAttributeMaxDynamicSharedMemorySize, SM_END);

    // zero accumulators
    cudaMemsetAsync(ps,    0, sizeof(float) * NODES1 * 128);
    cudaMemsetAsync(pcnt,  0, sizeof(float) * NODES1);
    cudaMemsetAsync(ps2,   0, sizeof(float) * NODES2 * 128);
    cudaMemsetAsync(pcnt2, 0, sizeof(float) * NODES2);

    // weight prep
    prep_w_kernel<<<128, 256>>>(Wl1, Wr1, pwh1, pwl1_);
    prep_w_kernel<<<128, 256>>>(Wl2, Wr2, pwh2, pwl2_);

    // ---- layer 1 ----
    agg1_kernel<<<(E_ * 32) / 256, 256>>>(x, src, dst, ps, pcnt);
    meandiv_kernel<<<(NODES1 * 32) / 256, 256>>>(ps, pcnt, NODES1);
    sage_wmma_kernel<<<NODES1 / 128, 256, SM_END>>>(ps, x, pwh1, pwl1_, bl1, ph1);
    score_kernel<<<(NODES1 * 32) / 256, 256>>>(ph1, pw1, psc1, NODES1);
    topk_kernel<<<B_, 1024>>>(psc1, pperm1, pinv1, N_, K1_);
    gate_kernel<<<(NODES2 * 32) / 256, 256>>>(ph1, psc1, pperm1, ph1p, NODES2);
    readout_kernel<<<B_, 512>>>(ph1p, px1, K1_);

    // ---- layer 2 ----
    agg2_kernel<<<(E_ * 32) / 256, 256>>>(ph1p, src, dst, pinv1, ps2, pcnt2);
    meandiv_kernel<<<(NODES2 * 32) / 256, 256>>>(ps2, pcnt2, NODES2);
    sage_wmma_kernel<<<NODES2 / 128, 256, SM_END>>>(ps2, ph1p, pwh2, pwl2_, bl2, ph2);
    score_kernel<<<(NODES2 * 32) / 256, 256>>>(ph2, pw2, psc2, NODES2);
    topk_kernel<<<B_, 1024>>>(psc2, pperm2, (int*)0, K1_, K2_);
    gate_kernel<<<(NODES3 * 32) / 256, 256>>>(ph2, psc2, pperm2, ph2p, NODES3);
    readout_kernel<<<B_, 512>>>(ph2p, px2, K2_);

    // ---- head ----
    mlp_kernel<<<B_, 128>>>(px1, px2, fW1, fb1, fW2, fb2, out);
}